// round 13
// baseline (speedup 1.0000x reference)
#include <cuda_runtime.h>
#include <cuda_bf16.h>
#include <cstdint>
#include <math.h>

// Problem constants
#define BATCH   8192
#define DIM     1024      // DIM1 == DIM2
#define SKETCH  8192
#define OUT     512
#define LN_EPS  1e-5f

#define MCAP    1024      // |J| <= 1024 (hard bound)
#define CCH     128       // column chunk for main kernel
#define TB      64        // batch rows per CTA (two independent 32-row halves)
#define NTHR    1024      // threads per CTA (32 warps; 16 per half)
#define SUBCL   16        // W staging sub-chunk per half (16 x 512 x 4B = 32KB)

// dynamic smem layout (floats): sp[CCH*TB] + WS0[SUBCL*OUT] + WS1[SUBCL*OUT]
#define SP_OFF     0
#define WS0_OFF    (CCH * TB)
#define WS1_OFF    (WS0_OFF + SUBCL * OUT)
#define DSM_FLOATS (WS1_OFF + SUBCL * OUT)
#define DSM_BYTES  (DSM_FLOATS * 4)          // 96 KB

// ---------------- device globals (scratch; no cudaMalloc allowed) ----------
__device__ unsigned int g_idx1[DIM];
__device__ unsigned int g_idx2[DIM];
__device__ int          g_m;
__device__ int          g_fallback;       // 1 if any column has >4 entries
__device__ int          g_colJ[MCAP];
__device__ int          g_cp1[MCAP + 1];
__device__ int          g_cp2[MCAP + 1];
__device__ unsigned int g_ent1[MCAP];     // (sign<<15) | i
__device__ unsigned int g_ent2[MCAP];
__device__ ulonglong2   g_rec[MCAP];      // packed per-column records
__device__ float        g_Wc[MCAP * OUT]; // compacted W rows

// -------- f32x2 packed-FMA helpers (PTX-only) ------------------------------
__device__ __forceinline__ unsigned long long pack2(float lo, float hi) {
    unsigned long long r;
    asm("mov.b64 %0, {%1, %2};" : "=l"(r) : "f"(lo), "f"(hi));
    return r;
}
__device__ __forceinline__ void unpack2(unsigned long long v, float& lo, float& hi) {
    asm("mov.b64 {%0, %1}, %2;" : "=f"(lo), "=f"(hi) : "l"(v));
}
__device__ __forceinline__ unsigned long long ffma2(unsigned long long a,
                                                    unsigned long long b,
                                                    unsigned long long c) {
    unsigned long long d;
    asm("fma.rn.f32x2 %0, %1, %2, %3;" : "=l"(d) : "l"(a), "l"(b), "l"(c));
    return d;
}
// apply packed sign: e bit10 set -> negate (XOR into fp32 sign bit)
__device__ __forceinline__ float sgnapply(float x, unsigned e) {
    return __int_as_float(__float_as_int(x) ^ (int)((e & 1024u) << 21));
}
// half-scoped named barrier (ids 1 and 2; 512 threads each)
__device__ __forceinline__ void half_bar(int id) {
    asm volatile("bar.sync %0, 512;" :: "r"(id) : "memory");
}

// -------- warp-shuffle block scan (1024 threads) ---------------------------
__device__ __forceinline__ int block_scan_incl(int val, int t, int* ws) {
    const unsigned full = 0xFFFFFFFFu;
    int lane = t & 31;
#pragma unroll
    for (int o = 1; o < 32; o <<= 1) {
        int n = __shfl_up_sync(full, val, o);
        if (lane >= o) val += n;
    }
    if (lane == 31) ws[t >> 5] = val;
    __syncthreads();
    if (t < 32) {
        int v = ws[t];
#pragma unroll
        for (int o = 1; o < 32; o <<= 1) {
            int n = __shfl_up_sync(full, v, o);
            if (t >= o) v += n;
        }
        ws[t] = v;
    }
    __syncthreads();
    if (t >= 32) val += ws[(t >> 5) - 1];
    return val;
}

// ---------------------------------------------------------------------------
// Kernel A: find the single nonzero per row of S1/S2. Coalesced float4 scan.
// ---------------------------------------------------------------------------
__global__ void k_extract(const float* __restrict__ S1,
                          const float* __restrict__ S2)
{
    int row = blockIdx.x;
    const float* S;
    unsigned int* outp;
    if (row < DIM) { S = S1; outp = g_idx1; }
    else           { S = S2; outp = g_idx2; row -= DIM; }

    const float4* p = (const float4*)(S + (size_t)row * SKETCH);
    int t = threadIdx.x;
#pragma unroll
    for (int k = 0; k < SKETCH / 4 / 256; k++) {
        int v4 = t + k * 256;
        float4 v = p[v4];
        int base = v4 * 4;
        if (v.x != 0.0f) outp[row] = (unsigned)(base + 0) | (v.x < 0.0f ? 0x80000000u : 0u);
        if (v.y != 0.0f) outp[row] = (unsigned)(base + 1) | (v.y < 0.0f ? 0x80000000u : 0u);
        if (v.z != 0.0f) outp[row] = (unsigned)(base + 2) | (v.z < 0.0f ? 0x80000000u : 0u);
        if (v.w != 0.0f) outp[row] = (unsigned)(base + 3) | (v.w < 0.0f ? 0x80000000u : 0u);
    }
}

// ---------------------------------------------------------------------------
// Kernel B: build compact structure + CSR + packed records. 1 CTA, 1024 thr.
// ---------------------------------------------------------------------------
__global__ void k_build()
{
    __shared__ int cnt[SKETCH];
    __shared__ int colcnt[MCAP];
    __shared__ int ws[32];
    __shared__ int sh_total;

    int t = threadIdx.x;

    for (int j = t; j < SKETCH; j += 1024) cnt[j] = 0;
    if (t == 0) g_fallback = 0;
    __syncthreads();

    unsigned u1 = g_idx1[t];
    unsigned u2 = g_idx2[t];
    atomicAdd(&cnt[u1 & (SKETCH - 1)], 1);
    atomicAdd(&cnt[u2 & (SKETCH - 1)], 1 << 16);
    __syncthreads();

    int q = 0;
    int qual[8];
#pragma unroll
    for (int u = 0; u < 8; u++) {
        int j = t * 8 + u;
        int c = cnt[j];
        qual[u] = ((c & 0xFFFF) > 0 && (c >> 16) > 0) ? 1 : 0;
        q += qual[u];
    }
    int incl = block_scan_incl(q, t, ws);
    int excl = incl - q;
    if (t == 1023) sh_total = incl;
    __syncthreads();
    int total = sh_total;

#pragma unroll
    for (int u = 0; u < 8; u++) {
        int j = t * 8 + u;
        if (qual[u]) { g_colJ[excl] = j; cnt[j] = excl; excl++; }
        else         { cnt[j] = -1; }
    }
    if (t == 0) g_m = total;
    __syncthreads();

    int c1 = cnt[u1 & (SKETCH - 1)];
    int c2 = cnt[u2 & (SKETCH - 1)];
#pragma unroll
    for (int s = 0; s < 2; s++) {
        int cc = s ? c2 : c1;
        unsigned uu = s ? u2 : u1;
        int* cp = s ? g_cp2 : g_cp1;
        unsigned int* ent = s ? g_ent2 : g_ent1;

        colcnt[t] = 0;
        __syncthreads();
        if (cc >= 0) atomicAdd(&colcnt[cc], 1);
        __syncthreads();

        int myc = colcnt[t];
        int inc2 = block_scan_incl(myc, t, ws);
        int ex = inc2 - myc;
        cp[t] = ex;
        if (t == 1023) cp[1024] = inc2;
        __syncthreads();
        colcnt[t] = ex;
        __syncthreads();
        if (cc >= 0) {
            int slot = atomicAdd(&colcnt[cc], 1);
            ent[slot] = (((uu >> 31) & 1u) << 15) | (unsigned)t;
        }
        __syncthreads();
    }

    // ---- packed records: per column, both sides, up to 4 entries ----
    if (t < total) {
        unsigned long long w[2];
#pragma unroll
        for (int s = 0; s < 2; s++) {
            const int* cp = s ? g_cp2 : g_cp1;
            const unsigned int* ent = s ? g_ent2 : g_ent1;
            int e0 = cp[t], e1 = cp[t + 1];
            int cnte = e1 - e0;
            if (cnte > 4) { atomicOr(&g_fallback, 1); cnte = 4; }
            unsigned long long u = 0;
            for (int k = 0; k < cnte; k++) {
                unsigned v = ent[e0 + k];
                unsigned i = v & 1023u;
                unsigned sg = (v >> 15) & 1u;
                u |= (unsigned long long)(i | (sg << 10)) << (11 * k);
            }
            u |= (unsigned long long)cnte << 60;
            w[s] = u;
        }
        ulonglong2 r;
        r.x = w[0];
        r.y = w[1];
        g_rec[t] = r;
    }
}

// ---------------------------------------------------------------------------
// Kernel B2: gather compacted W rows.
// ---------------------------------------------------------------------------
__global__ void k_wgather(const float* __restrict__ W)
{
    int c = blockIdx.x;
    if (c < g_m) {
        g_Wc[(size_t)c * OUT + threadIdx.x] =
            W[(size_t)g_colJ[c] * OUT + threadIdx.x];
    }
}

// ---------------------------------------------------------------------------
// GEMM micro-step: lane = 1 row, warp = 32 cols (16 packed col-pairs).
// ---------------------------------------------------------------------------
#define GEMM_STEP(base, c2_)                                                   \
    {                                                                          \
        float v = sp[((base) + (c2_)) * TB + myrow];                           \
        unsigned long long v2 = pack2(v, v);                                   \
        const ulonglong2* wp = (const ulonglong2*)&WSh[(c2_) * OUT + o0];      \
        ulonglong2 w0 = wp[0];                                                 \
        ulonglong2 w1 = wp[1];                                                 \
        ulonglong2 w2 = wp[2];                                                 \
        ulonglong2 w3 = wp[3];                                                 \
        ulonglong2 w4 = wp[4];                                                 \
        ulonglong2 w5 = wp[5];                                                 \
        ulonglong2 w6 = wp[6];                                                 \
        ulonglong2 w7 = wp[7];                                                 \
        acc2[0]  = ffma2(v2, w0.x, acc2[0]);                                   \
        acc2[1]  = ffma2(v2, w0.y, acc2[1]);                                   \
        acc2[2]  = ffma2(v2, w1.x, acc2[2]);                                   \
        acc2[3]  = ffma2(v2, w1.y, acc2[3]);                                   \
        acc2[4]  = ffma2(v2, w2.x, acc2[4]);                                   \
        acc2[5]  = ffma2(v2, w2.y, acc2[5]);                                   \
        acc2[6]  = ffma2(v2, w3.x, acc2[6]);                                   \
        acc2[7]  = ffma2(v2, w3.y, acc2[7]);                                   \
        acc2[8]  = ffma2(v2, w4.x, acc2[8]);                                   \
        acc2[9]  = ffma2(v2, w4.y, acc2[9]);                                   \
        acc2[10] = ffma2(v2, w5.x, acc2[10]);                                  \
        acc2[11] = ffma2(v2, w5.y, acc2[11]);                                  \
        acc2[12] = ffma2(v2, w6.x, acc2[12]);                                  \
        acc2[13] = ffma2(v2, w6.y, acc2[13]);                                  \
        acc2[14] = ffma2(v2, w7.x, acc2[14]);                                  \
        acc2[15] = ffma2(v2, w7.y, acc2[15]);                                  \
    }

// ---------------------------------------------------------------------------
// Main fused kernel. TB=64 rows/CTA, 1024 threads, 128 CTAs.
//  TWO INDEPENDENT 512-thread HALVES (warps 0-15: rows 0-31; 16-31: rows
//  32-63), each with its own W staging buffer and named barrier — no
//  full-CTA syncs. The halves drift out of phase, so one half's FFMA2-dense
//  GEMM overlaps the other half's gather/staging in the issue slots left by
//  the FFMA2 bank-conflict rt.
//  Gather: packed records, row-pair (r, r+16) per item.
//  GEMM: warp = 32 cols, lane = 1 row; W via warp-uniform broadcast LDS.128.
//  Epilogue: per-half LayerNorm (bias folded into acc init) + ReLU.
// ---------------------------------------------------------------------------
__global__ void __launch_bounds__(NTHR, 1)
k_main(const float* __restrict__ x1, const float* __restrict__ x2,
       const float* __restrict__ bias, const float* __restrict__ gamma,
       const float* __restrict__ beta, float* __restrict__ out)
{
    extern __shared__ __align__(16) float dsm[];
    float* sp = dsm + SP_OFF;     // [CCH][TB] product tile (shared, disjoint rows)

    int tid   = threadIdx.x;
    int lane  = tid & 31;
    int wrp   = tid >> 5;
    int half  = wrp >> 4;         // 0 or 1
    int wl    = wrp & 15;         // warp within half
    int htid  = tid & 511;        // thread within half
    int barid = half + 1;         // named barrier id (1 or 2)
    int rbase = half * 32;        // this half's row base
    int myrow = rbase + lane;     // GEMM row for this thread
    int o0    = wl * 32;          // 32 output cols per warp
    int b0    = blockIdx.x * TB;

    float* WSh = dsm + (half ? WS1_OFF : WS0_OFF);   // per-half W staging

    int m  = g_m;
    int fb = g_fallback;

    // accumulators: acc2[k] = row myrow, cols (o0+2k, o0+2k+1)
    unsigned long long acc2[16];
    {
        const ulonglong2* bq = (const ulonglong2*)(bias + o0);
#pragma unroll
        for (int q = 0; q < 8; q++) {
            ulonglong2 bb = __ldg(bq + q);
            acc2[2 * q]     = bb.x;
            acc2[2 * q + 1] = bb.y;
        }
    }

    int nch = (m + CCH - 1) / CCH;
    for (int ch = 0; ch < nch; ch++) {
        int ck0 = ch * CCH;
        int Cn  = min(CCH, m - ck0);

        // ---- gather this half's 32 rows: v[c][r] = s1(c,r)*s2(c,r) ----
        if (!fb) {
            int nw = Cn * 16;                    // 16 row-pairs per column
            for (int p = htid; p < nw; p += 512) {
                int cl = p >> 4;
                int r  = rbase + (p & 15);       // rows r and r+16
                int c  = ck0 + cl;
                ulonglong2 rec = __ldg(&g_rec[c]);
                size_t ro0 = (size_t)(b0 + r) * DIM;
                size_t ro1 = (size_t)(b0 + r + 16) * DIM;

                unsigned long long u = rec.x;
                int cnt1 = (int)(u >> 60);
                unsigned e = (unsigned)u & 0x7FFu;
                float s1a = sgnapply(__ldg(&x1[ro0 + (e & 1023u)]), e);
                float s1b = sgnapply(__ldg(&x1[ro1 + (e & 1023u)]), e);
#pragma unroll
                for (int k = 1; k < 4; k++) {
                    if (k < cnt1) {
                        e = (unsigned)(u >> (11 * k)) & 0x7FFu;
                        s1a += sgnapply(__ldg(&x1[ro0 + (e & 1023u)]), e);
                        s1b += sgnapply(__ldg(&x1[ro1 + (e & 1023u)]), e);
                    }
                }
                u = rec.y;
                int cnt2 = (int)(u >> 60);
                e = (unsigned)u & 0x7FFu;
                float s2a = sgnapply(__ldg(&x2[ro0 + (e & 1023u)]), e);
                float s2b = sgnapply(__ldg(&x2[ro1 + (e & 1023u)]), e);
#pragma unroll
                for (int k = 1; k < 4; k++) {
                    if (k < cnt2) {
                        e = (unsigned)(u >> (11 * k)) & 0x7FFu;
                        s2a += sgnapply(__ldg(&x2[ro0 + (e & 1023u)]), e);
                        s2b += sgnapply(__ldg(&x2[ro1 + (e & 1023u)]), e);
                    }
                }
                sp[cl * TB + r]      = s1a * s2a;
                sp[cl * TB + r + 16] = s1b * s2b;
            }
        } else {
            int nw = Cn * 32;
            for (int p = htid; p < nw; p += 512) {
                int cl = p >> 5;
                int r  = rbase + (p & 31);
                int c  = ck0 + cl;
                size_t rowoff = (size_t)(b0 + r) * DIM;

                float s1 = 0.0f;
                int e0 = __ldg(&g_cp1[c]), e1 = __ldg(&g_cp1[c + 1]);
                for (int e = e0; e < e1; e++) {
                    unsigned u = __ldg(&g_ent1[e]);
                    float x = __ldg(&x1[rowoff + (u & 1023u)]);
                    s1 += (u & 0x8000u) ? -x : x;
                }
                float s2 = 0.0f;
                int f0 = __ldg(&g_cp2[c]), f1 = __ldg(&g_cp2[c + 1]);
                for (int e = f0; e < f1; e++) {
                    unsigned u = __ldg(&g_ent2[e]);
                    float x = __ldg(&x2[rowoff + (u & 1023u)]);
                    s2 += (u & 0x8000u) ? -x : x;
                }
                sp[cl * TB + r] = s1 * s2;
            }
        }
        half_bar(barid);

        // ---- GEMM over sub-chunks: stage 16 W rows into WSh, then FFMA2 ----
        int nsub = (Cn + SUBCL - 1) / SUBCL;
        for (int sub = 0; sub < nsub; sub++) {
            {   // stage W: 16 rows x 512 floats; 512 threads x 4 float4,
                // lane-consecutive -> perfectly coalesced
                int row = htid >> 5;             // 0..15
                int f4  = htid & 31;
                const float4* src = (const float4*)
                    &g_Wc[(size_t)(ck0 + sub * SUBCL + row) * OUT];
                float4* dstW = (float4*)&WSh[row * OUT];
#pragma unroll
                for (int k = 0; k < 4; k++)
                    dstW[f4 + k * 32] = __ldg(&src[f4 + k * 32]);
            }
            half_bar(barid);

            int base = sub * SUBCL;
            int Csub = min(SUBCL, Cn - base);
            if (Csub == SUBCL) {
#pragma unroll 2
                for (int c2 = 0; c2 < SUBCL; c2++) GEMM_STEP(base, c2)
            } else {
                for (int c2 = 0; c2 < Csub; c2++) GEMM_STEP(base, c2)
            }
            half_bar(barid);   // WSh about to be restaged (or reused by LN)
        }
        // (next chunk's gather rewrites this half's sp rows only after the
        //  half's own GEMM is done — guarded by the barrier above)
    }

    // -------- LayerNorm per half: reduce each row across the 16 warps ------
    float* red_s = WSh;                  // [32][17]
    float* red_q = WSh + 32 * 17;
    float* shmu  = WSh + 2 * 32 * 17;
    float* shrs  = shmu + 32;
    {
        float s = 0.0f, q = 0.0f;
#pragma unroll
        for (int k = 0; k < 16; k++) {
            float lo, hi;
            unpack2(acc2[k], lo, hi);
            s += lo + hi;
            q += lo * lo + hi * hi;
        }
        red_s[lane * 17 + wl] = s;
        red_q[lane * 17 + wl] = q;
    }
    half_bar(barid);
    if (htid < 32) {
        float s = 0.0f, q = 0.0f;
#pragma unroll
        for (int w = 0; w < 16; w++) {
            s += red_s[htid * 17 + w];
            q += red_q[htid * 17 + w];
        }
        float mu  = s * (1.0f / OUT);
        float var = q * (1.0f / OUT) - mu * mu;
        shmu[htid] = mu;
        shrs[htid] = rsqrtf(var + LN_EPS);
    }
    half_bar(barid);

    // -------- normalize, affine, ReLU, store -------------------------------
    {
        float mu = shmu[lane];
        float rs = shrs[lane];
        float* dst = out + (size_t)(b0 + myrow) * OUT + o0;
#pragma unroll
        for (int q = 0; q < 4; q++) {
            float4 g4 = __ldg((const float4*)(gamma + o0 + 8 * q));
            float4 g5 = __ldg((const float4*)(gamma + o0 + 8 * q + 4));
            float4 e4 = __ldg((const float4*)(beta  + o0 + 8 * q));
            float4 e5 = __ldg((const float4*)(beta  + o0 + 8 * q + 4));
            float lo0, hi0, lo1, hi1, lo2, hi2, lo3, hi3;
            unpack2(acc2[4 * q],     lo0, hi0);
            unpack2(acc2[4 * q + 1], lo1, hi1);
            unpack2(acc2[4 * q + 2], lo2, hi2);
            unpack2(acc2[4 * q + 3], lo3, hi3);
            float4 o4, o5;
            o4.x = fmaxf((lo0 - mu) * rs * g4.x + e4.x, 0.0f);
            o4.y = fmaxf((hi0 - mu) * rs * g4.y + e4.y, 0.0f);
            o4.z = fmaxf((lo1 - mu) * rs * g4.z + e4.z, 0.0f);
            o4.w = fmaxf((hi1 - mu) * rs * g4.w + e4.w, 0.0f);
            o5.x = fmaxf((lo2 - mu) * rs * g5.x + e5.x, 0.0f);
            o5.y = fmaxf((hi2 - mu) * rs * g5.y + e5.y, 0.0f);
            o5.z = fmaxf((lo3 - mu) * rs * g5.z + e5.z, 0.0f);
            o5.w = fmaxf((hi3 - mu) * rs * g5.w + e5.w, 0.0f);
            *(float4*)(dst + 8 * q)     = o4;
            *(float4*)(dst + 8 * q + 4) = o5;
        }
    }
}

// ---------------------------------------------------------------------------
extern "C" void kernel_launch(void* const* d_in, const int* in_sizes, int n_in,
                              void* d_out, int out_size)
{
    const float* x1    = (const float*)d_in[0];
    const float* x2    = (const float*)d_in[1];
    const float* S1    = (const float*)d_in[2];
    const float* S2    = (const float*)d_in[3];
    const float* W     = (const float*)d_in[4];
    const float* b     = (const float*)d_in[5];
    const float* gamma = (const float*)d_in[6];
    const float* beta  = (const float*)d_in[7];
    float* out = (float*)d_out;

    // attribute set (not an allocation); idempotent and graph-legal
    cudaFuncSetAttribute(k_main, cudaFuncAttributeMaxDynamicSharedMemorySize,
                         DSM_BYTES);

    k_extract<<<2 * DIM, 256>>>(S1, S2);
    k_build<<<1, 1024>>>();
    k_wgather<<<MCAP, OUT>>>(W);
    k_main<<<BATCH / TB, NTHR, DSM_BYTES>>>(x1, x2, b, gamma, beta, out);
}

// round 15
// speedup vs baseline: 1.3379x; 1.3379x over previous
#include <cuda_runtime.h>
#include <cuda_bf16.h>
#include <cstdint>
#include <math.h>

// Problem constants
#define BATCH   8192
#define DIM     1024
#define SKETCH  8192
#define OUT     512
#define LN_EPS  1e-5f

#define MCAP    1024      // |J| <= 1024 (hard bound)
#define TB      64        // batch rows per CTA
#define NTHR    1024      // 32 warps
#define KCH     128       // K per chunk (64 kpairs)
#define APKS    72        // Apk row stride in words (bank-bijective)
#define WBS     72        // WB staging stride in words

// -------- dynamic smem layout (bytes) --------------------------------------
#define OFF_AH   0                       // Apk_hi [64 kp][72 w] = 18432
#define OFF_AL   18432                   // Apk_lo             = 18432
#define OFF_WH   36864                   // WB_hi  [128 n][72 w] = 36864
#define OFF_WL   73728                   // WB_lo              = 36864
#define OFF_BIAS 110592                  // 512 f
#define OFF_PS   112640                  // [64][8] f
#define OFF_PQ   114688                  // [64][8] f
#define OFF_MU   116736                  // 64 f
#define OFF_RS   116992                  // 64 f
#define DSM_BYTES 117760

// ---------------- device globals (scratch; no cudaMalloc allowed) ----------
__device__ unsigned int g_idx1[DIM];
__device__ unsigned int g_idx2[DIM];
__device__ int          g_m;
__device__ int          g_fallback;
__device__ int          g_colJ[MCAP];
__device__ int          g_cp1[MCAP + 1];
__device__ int          g_cp2[MCAP + 1];
__device__ unsigned int g_ent1[MCAP];
__device__ unsigned int g_ent2[MCAP];
__device__ ulonglong2   g_rec[MCAP];
// pre-split packed W: [n=512][kpair=512] bf16x2 words (1MB each)
__device__ unsigned int g_WBh[512 * 512];
__device__ unsigned int g_WBl[512 * 512];

// -------- helpers ----------------------------------------------------------
__device__ __forceinline__ float sgnapply(float x, unsigned e) {
    return __int_as_float(__float_as_int(x) ^ (int)((e & 1024u) << 21));
}
// bf16 3-split store: hi + lo halfwords into packed [kpair][row] tiles
__device__ __forceinline__ void put_split(char* bh, char* bl, int cl, int r, float v) {
    __nv_bfloat16 h = __float2bfloat16(v);
    __nv_bfloat16 l = __float2bfloat16(v - __bfloat162float(h));
    unsigned off = (unsigned)(((cl >> 1) * APKS + r) * 4 + (cl & 1) * 2);
    *(__nv_bfloat16*)(bh + off) = h;
    *(__nv_bfloat16*)(bl + off) = l;
}
// m16n8k16 bf16 MMA, fp32 accumulate in place
__device__ __forceinline__ void mma_bf16(float* d, const unsigned* a, const unsigned* b) {
    asm volatile(
        "mma.sync.aligned.m16n8k16.row.col.f32.bf16.bf16.f32 "
        "{%0,%1,%2,%3}, {%4,%5,%6,%7}, {%8,%9}, {%0,%1,%2,%3};"
        : "+f"(d[0]), "+f"(d[1]), "+f"(d[2]), "+f"(d[3])
        : "r"(a[0]), "r"(a[1]), "r"(a[2]), "r"(a[3]), "r"(b[0]), "r"(b[1]));
}

// -------- warp-shuffle block scan (1024 threads) ---------------------------
__device__ __forceinline__ int block_scan_incl(int val, int t, int* ws) {
    const unsigned full = 0xFFFFFFFFu;
    int lane = t & 31;
#pragma unroll
    for (int o = 1; o < 32; o <<= 1) {
        int n = __shfl_up_sync(full, val, o);
        if (lane >= o) val += n;
    }
    if (lane == 31) ws[t >> 5] = val;
    __syncthreads();
    if (t < 32) {
        int v = ws[t];
#pragma unroll
        for (int o = 1; o < 32; o <<= 1) {
            int n = __shfl_up_sync(full, v, o);
            if (t >= o) v += n;
        }
        ws[t] = v;
    }
    __syncthreads();
    if (t >= 32) val += ws[(t >> 5) - 1];
    return val;
}

// ---------------------------------------------------------------------------
// Kernel A: find the single nonzero per row of S1/S2.
// ---------------------------------------------------------------------------
__global__ void k_extract(const float* __restrict__ S1,
                          const float* __restrict__ S2)
{
    int row = blockIdx.x;
    const float* S;
    unsigned int* outp;
    if (row < DIM) { S = S1; outp = g_idx1; }
    else           { S = S2; outp = g_idx2; row -= DIM; }

    const float4* p = (const float4*)(S + (size_t)row * SKETCH);
    int t = threadIdx.x;
#pragma unroll
    for (int k = 0; k < SKETCH / 4 / 256; k++) {
        int v4 = t + k * 256;
        float4 v = p[v4];
        int base = v4 * 4;
        if (v.x != 0.0f) outp[row] = (unsigned)(base + 0) | (v.x < 0.0f ? 0x80000000u : 0u);
        if (v.y != 0.0f) outp[row] = (unsigned)(base + 1) | (v.y < 0.0f ? 0x80000000u : 0u);
        if (v.z != 0.0f) outp[row] = (unsigned)(base + 2) | (v.z < 0.0f ? 0x80000000u : 0u);
        if (v.w != 0.0f) outp[row] = (unsigned)(base + 3) | (v.w < 0.0f ? 0x80000000u : 0u);
    }
}

// ---------------------------------------------------------------------------
// Kernel B: build compact structure + CSR + packed records. 1 CTA, 1024 thr.
// ---------------------------------------------------------------------------
__global__ void k_build()
{
    __shared__ int cnt[SKETCH];
    __shared__ int colcnt[MCAP];
    __shared__ int ws[32];
    __shared__ int sh_total;

    int t = threadIdx.x;
    for (int j = t; j < SKETCH; j += 1024) cnt[j] = 0;
    if (t == 0) g_fallback = 0;
    __syncthreads();

    unsigned u1 = g_idx1[t];
    unsigned u2 = g_idx2[t];
    atomicAdd(&cnt[u1 & (SKETCH - 1)], 1);
    atomicAdd(&cnt[u2 & (SKETCH - 1)], 1 << 16);
    __syncthreads();

    int q = 0;
    int qual[8];
#pragma unroll
    for (int u = 0; u < 8; u++) {
        int j = t * 8 + u;
        int c = cnt[j];
        qual[u] = ((c & 0xFFFF) > 0 && (c >> 16) > 0) ? 1 : 0;
        q += qual[u];
    }
    int incl = block_scan_incl(q, t, ws);
    int excl = incl - q;
    if (t == 1023) sh_total = incl;
    __syncthreads();
    int total = sh_total;

#pragma unroll
    for (int u = 0; u < 8; u++) {
        int j = t * 8 + u;
        if (qual[u]) { g_colJ[excl] = j; cnt[j] = excl; excl++; }
        else         { cnt[j] = -1; }
    }
    if (t == 0) g_m = total;
    __syncthreads();

    int c1 = cnt[u1 & (SKETCH - 1)];
    int c2 = cnt[u2 & (SKETCH - 1)];
#pragma unroll
    for (int s = 0; s < 2; s++) {
        int cc = s ? c2 : c1;
        unsigned uu = s ? u2 : u1;
        int* cp = s ? g_cp2 : g_cp1;
        unsigned int* ent = s ? g_ent2 : g_ent1;

        colcnt[t] = 0;
        __syncthreads();
        if (cc >= 0) atomicAdd(&colcnt[cc], 1);
        __syncthreads();

        int myc = colcnt[t];
        int inc2 = block_scan_incl(myc, t, ws);
        int ex = inc2 - myc;
        cp[t] = ex;
        if (t == 1023) cp[1024] = inc2;
        __syncthreads();
        colcnt[t] = ex;
        __syncthreads();
        if (cc >= 0) {
            int slot = atomicAdd(&colcnt[cc], 1);
            ent[slot] = (((uu >> 31) & 1u) << 15) | (unsigned)t;
        }
        __syncthreads();
    }

    if (t < total) {
        unsigned long long w[2];
#pragma unroll
        for (int s = 0; s < 2; s++) {
            const int* cp = s ? g_cp2 : g_cp1;
            const unsigned int* ent = s ? g_ent2 : g_ent1;
            int e0 = cp[t], e1 = cp[t + 1];
            int cnte = e1 - e0;
            if (cnte > 4) { atomicOr(&g_fallback, 1); cnte = 4; }
            unsigned long long u = 0;
            for (int k = 0; k < cnte; k++) {
                unsigned v = ent[e0 + k];
                u |= (unsigned long long)((v & 1023u) | (((v >> 15) & 1u) << 10)) << (11 * k);
            }
            u |= (unsigned long long)cnte << 60;
            w[s] = u;
        }
        ulonglong2 r;
        r.x = w[0];
        r.y = w[1];
        g_rec[t] = r;
    }
}

// ---------------------------------------------------------------------------
// Kernel Bw: pre-split W into packed bf16x2 hi/lo, layout [n][kpair].
// Word (n, kp) = {W[colJ[2kp]][n], W[colJ[2kp+1]][n]} as bf16 pair.
// kp-fast thread order -> coalesced writes.
// ---------------------------------------------------------------------------
__global__ void k_wprep(const float* __restrict__ W)
{
    int m = g_m;
    int idx = blockIdx.x * 256 + threadIdx.x;   // 512 n x 512 kp
    int kp = idx & 511;
    int n  = idx >> 9;
    int c0 = 2 * kp, c1 = 2 * kp + 1;
    float v0 = (c0 < m) ? __ldg(&W[(size_t)g_colJ[c0] * OUT + n]) : 0.0f;
    float v1 = (c1 < m) ? __ldg(&W[(size_t)g_colJ[c1] * OUT + n]) : 0.0f;
    __nv_bfloat16 h0 = __float2bfloat16(v0);
    __nv_bfloat16 l0 = __float2bfloat16(v0 - __bfloat162float(h0));
    __nv_bfloat16 h1 = __float2bfloat16(v1);
    __nv_bfloat16 l1 = __float2bfloat16(v1 - __bfloat162float(h1));
    unsigned wh = (unsigned)__bfloat16_as_ushort(h0) |
                  ((unsigned)__bfloat16_as_ushort(h1) << 16);
    unsigned wl = (unsigned)__bfloat16_as_ushort(l0) |
                  ((unsigned)__bfloat16_as_ushort(l1) << 16);
    g_WBh[n * 512 + kp] = wh;
    g_WBl[n * 512 + kp] = wl;
}

// ---------------------------------------------------------------------------
// Main fused kernel. TB=64 rows/CTA, 1024 threads (32 warps), 128 CTAs.
//  Gather (records) -> split-bf16 packed A tiles; GEMM via mma.sync bf16
//  m16n8k16, 3-split (AhBh + AhBl + AlBh), fp32 acc in registers.
//  Warp (mt, ng): rows [mt*16,+16), cols [ng*16,+16) per 128-col n-tile.
//  Epilogue: +bias, LayerNorm (shfl + smem partials), ReLU.
// ---------------------------------------------------------------------------
__global__ void __launch_bounds__(NTHR, 1)
k_main(const float* __restrict__ x1, const float* __restrict__ x2,
       const float* __restrict__ bias, const float* __restrict__ gamma,
       const float* __restrict__ beta, float* __restrict__ out)
{
    extern __shared__ __align__(16) char dsm[];
    const unsigned* AHw = (const unsigned*)(dsm + OFF_AH);
    const unsigned* ALw = (const unsigned*)(dsm + OFF_AL);
    unsigned* WHs = (unsigned*)(dsm + OFF_WH);
    unsigned* WLs = (unsigned*)(dsm + OFF_WL);

    int tid  = threadIdx.x;
    int lane = tid & 31;
    int wrp  = tid >> 5;
    int g    = lane >> 2;         // 0..7
    int t4   = lane & 3;          // 0..3
    int mt   = wrp >> 3;          // 0..3  -> rows [mt*16, +16)
    int ng   = wrp & 7;           // 0..7  -> cols [ng*16, +16) within n-tile
    int b0   = blockIdx.x * TB;

    int m  = g_m;
    int fb = g_fallback;
    int nch = (m + KCH - 1) / KCH;

    for (int i = tid; i < OUT; i += NTHR)
        *(float*)(dsm + OFF_BIAS + i * 4) = __ldg(&bias[i]);

    // accumulators: acc[nt][n8][frag]; frag = {(g,2t),(g,2t+1),(g+8,2t),(g+8,2t+1)}
    float acc[4][2][4];
#pragma unroll
    for (int a = 0; a < 4; a++)
#pragma unroll
        for (int b = 0; b < 2; b++)
#pragma unroll
            for (int c = 0; c < 4; c++) acc[a][b][c] = 0.0f;

    for (int ch = 0; ch < nch; ch++) {
        int ck0 = ch * KCH;
        int Cn  = min(KCH, m - ck0);

        // zero A tiles (hi+lo contiguous, 36864 B)
        for (int i = tid; i < 2304; i += NTHR)
            ((uint4*)dsm)[i] = make_uint4(0, 0, 0, 0);
        __syncthreads();

        // ---- gather -> split bf16 packed A ----
        if (!fb) {
            int nw = Cn * 32;
            for (int p = tid; p < nw; p += NTHR) {
                int cl = p >> 5;
                int r  = p & 31;
                int c  = ck0 + cl;
                ulonglong2 rec = __ldg(&g_rec[c]);
                size_t ro0 = (size_t)(b0 + r) * DIM;
                size_t ro1 = (size_t)(b0 + r + 32) * DIM;

                unsigned long long u = rec.x;
                int cnt1 = (int)(u >> 60);
                unsigned e = (unsigned)u & 0x7FFu;
                float s1a = sgnapply(__ldg(&x1[ro0 + (e & 1023u)]), e);
                float s1b = sgnapply(__ldg(&x1[ro1 + (e & 1023u)]), e);
#pragma unroll
                for (int k = 1; k < 4; k++) {
                    if (k < cnt1) {
                        e = (unsigned)(u >> (11 * k)) & 0x7FFu;
                        s1a += sgnapply(__ldg(&x1[ro0 + (e & 1023u)]), e);
                        s1b += sgnapply(__ldg(&x1[ro1 + (e & 1023u)]), e);
                    }
                }
                u = rec.y;
                int cnt2 = (int)(u >> 60);
                e = (unsigned)u & 0x7FFu;
                float s2a = sgnapply(__ldg(&x2[ro0 + (e & 1023u)]), e);
                float s2b = sgnapply(__ldg(&x2[ro1 + (e & 1023u)]), e);
#pragma unroll
                for (int k = 1; k < 4; k++) {
                    if (k < cnt2) {
                        e = (unsigned)(u >> (11 * k)) & 0x7FFu;
                        s2a += sgnapply(__ldg(&x2[ro0 + (e & 1023u)]), e);
                        s2b += sgnapply(__ldg(&x2[ro1 + (e & 1023u)]), e);
                    }
                }
                put_split(dsm + OFF_AH, dsm + OFF_AL, cl, r,      s1a * s2a);
                put_split(dsm + OFF_AH, dsm + OFF_AL, cl, r + 32, s1b * s2b);
            }
        } else {
            int nw = Cn * TB;
            for (int p = tid; p < nw; p += NTHR) {
                int cl = p >> 6;
                int r  = p & 63;
                int c  = ck0 + cl;
                size_t rowoff = (size_t)(b0 + r) * DIM;

                float s1 = 0.0f;
                int e0 = __ldg(&g_cp1[c]), e1 = __ldg(&g_cp1[c + 1]);
                for (int e = e0; e < e1; e++) {
                    unsigned u = __ldg(&g_ent1[e]);
                    float x = __ldg(&x1[rowoff + (u & 1023u)]);
                    s1 += (u & 0x8000u) ? -x : x;
                }
                float s2 = 0.0f;
                int f0 = __ldg(&g_cp2[c]), f1 = __ldg(&g_cp2[c + 1]);
                for (int e = f0; e < f1; e++) {
                    unsigned u = __ldg(&g_ent2[e]);
                    float x = __ldg(&x2[rowoff + (u & 1023u)]);
                    s2 += (u & 0x8000u) ? -x : x;
                }
                put_split(dsm + OFF_AH, dsm + OFF_AL, cl, r, s1 * s2);
            }
        }
        __syncthreads();

        // ---- 4 n-tiles of 128 cols ----
#pragma unroll
        for (int nt = 0; nt < 4; nt++) {
            // stage WB slice [128 n][64 kp] -> stride-72 smem
            for (int i = tid; i < 8192; i += NTHR) {
                int n  = i >> 6;
                int kp = i & 63;
                size_t src = (size_t)(nt * 128 + n) * 512 + ch * 64 + kp;
                WHs[n * WBS + kp] = g_WBh[src];
                WLs[n * WBS + kp] = g_WBl[src];
            }
            __syncthreads();

            int arow = mt * 16 + g;
#pragma unroll
            for (int ks = 0; ks < 8; ks++) {
                unsigned ah[4], al[4];
                int kpa = ks * 8 + t4;
                ah[0] = AHw[kpa * APKS + arow];
                ah[1] = AHw[kpa * APKS + arow + 8];
                ah[2] = AHw[(kpa + 4) * APKS + arow];
                ah[3] = AHw[(kpa + 4) * APKS + arow + 8];
                al[0] = ALw[kpa * APKS + arow];
                al[1] = ALw[kpa * APKS + arow + 8];
                al[2] = ALw[(kpa + 4) * APKS + arow];
                al[3] = ALw[(kpa + 4) * APKS + arow + 8];
#pragma unroll
                for (int n8 = 0; n8 < 2; n8++) {
                    int nrow = ng * 16 + n8 * 8 + g;
                    unsigned bh[2], bl[2];
                    bh[0] = WHs[nrow * WBS + kpa];
                    bh[1] = WHs[nrow * WBS + kpa + 4];
                    bl[0] = WLs[nrow * WBS + kpa];
                    bl[1] = WLs[nrow * WBS + kpa + 4];
                    mma_bf16(acc[nt][n8], ah, bh);
                    mma_bf16(acc[nt][n8], ah, bl);
                    mma_bf16(acc[nt][n8], al, bh);
                }
            }
            __syncthreads();   // WB restaged next nt (A reread only, safe)
        }
    }

    // -------- epilogue: +bias, LN stats --------------------------------
    float* PS = (float*)(dsm + OFF_PS);
    float* PQ = (float*)(dsm + OFF_PQ);
    float sA = 0.0f, qA = 0.0f, sB = 0.0f, qB = 0.0f;
#pragma unroll
    for (int nt = 0; nt < 4; nt++)
#pragma unroll
        for (int n8 = 0; n8 < 2; n8++) {
            int col = nt * 128 + ng * 16 + n8 * 8 + 2 * t4;
            float2 bb = *(float2*)(dsm + OFF_BIAS + col * 4);
            float* a4 = acc[nt][n8];
            a4[0] += bb.x; a4[1] += bb.y;
            a4[2] += bb.x; a4[3] += bb.y;
            sA += a4[0] + a4[1]; qA += a4[0] * a4[0] + a4[1] * a4[1];
            sB += a4[2] + a4[3]; qB += a4[2] * a4[2] + a4[3] * a4[3];
        }
#pragma unroll
    for (int o = 1; o < 4; o <<= 1) {
        sA += __shfl_xor_sync(0xFFFFFFFFu, sA, o);
        qA += __shfl_xor_sync(0xFFFFFFFFu, qA, o);
        sB += __shfl_xor_sync(0xFFFFFFFFu, sB, o);
        qB += __shfl_xor_sync(0xFFFFFFFFu, qB, o);
    }
    if (t4 == 0) {
        int rA = mt * 16 + g, rB = rA + 8;
        PS[rA * 8 + ng] = sA; PQ[rA * 8 + ng] = qA;
        PS[rB * 8 + ng] = sB; PQ[rB * 8 + ng] = qB;
    }
    __syncthreads();
    if (tid < TB) {
        float s = 0.0f, q = 0.0f;
#pragma unroll
        for (int w = 0; w < 8; w++) { s += PS[tid * 8 + w]; q += PQ[tid * 8 + w]; }
        float mu  = s * (1.0f / OUT);
        float var = q * (1.0f / OUT) - mu * mu;
        *(float*)(dsm + OFF_MU + tid * 4) = mu;
        *(float*)(dsm + OFF_RS + tid * 4) = rsqrtf(var + LN_EPS);
    }
    __syncthreads();

    // -------- normalize + affine + ReLU + store ------------------------
    {
        int rA = mt * 16 + g, rB = rA + 8;
        float muA = *(float*)(dsm + OFF_MU + rA * 4);
        float rsA = *(float*)(dsm + OFF_RS + rA * 4);
        float muB = *(float*)(dsm + OFF_MU + rB * 4);
        float rsB = *(float*)(dsm + OFF_RS + rB * 4);
        float* outA = out + (size_t)(b0 + rA) * OUT;
        float* outB = out + (size_t)(b0 + rB) * OUT;
#pragma unroll
        for (int nt = 0; nt < 4; nt++)
#pragma unroll
            for (int n8 = 0; n8 < 2; n8++) {
                int col = nt * 128 + ng * 16 + n8 * 8 + 2 * t4;
                float2 gg = __ldg((const float2*)(gamma + col));
                float2 ee = __ldg((const float2*)(beta + col));
                const float* a4 = acc[nt][n8];
                float2 oA, oB;
                oA.x = fmaxf((a4[0] - muA) * rsA * gg.x + ee.x, 0.0f);
                oA.y = fmaxf((a4[1] - muA) * rsA * gg.y + ee.y, 0.0f);
                oB.x = fmaxf((a4[2] - muB) * rsB * gg.x + ee.x, 0.0f);
                oB.y = fmaxf((a4[3] - muB) * rsB * gg.y + ee.y, 0.0f);
                *(float2*)(outA + col) = oA;
                *(float2*)(outB + col) = oB;
            }
    }
}

// ---------------------------------------------------------------------------
extern "C" void kernel_launch(void* const* d_in, const int* in_sizes, int n_in,
                              void* d_out, int out_size)
{
    const float* x1    = (const float*)d_in[0];
    const float* x2    = (const float*)d_in[1];
    const float* S1    = (const float*)d_in[2];
    const float* S2    = (const float*)d_in[3];
    const float* W     = (const float*)d_in[4];
    const float* b     = (const float*)d_in[5];
    const float* gamma = (const float*)d_in[6];
    const float* beta  = (const float*)d_in[7];
    float* out = (float*)d_out;

    cudaFuncSetAttribute(k_main, cudaFuncAttributeMaxDynamicSharedMemorySize,
                         DSM_BYTES);

    k_extract<<<2 * DIM, 256>>>(S1, S2);
    k_build<<<1, 1024>>>();
    k_wprep<<<1024, 256>>>(W);
    k_main<<<BATCH / TB, NTHR, DSM_BYTES>>>(x1, x2, b, gamma, beta, out);
}